// round 2
// baseline (speedup 1.0000x reference)
#include <cuda_runtime.h>
#include <cuda_bf16.h>
#include <cstdint>

// ---------------------------------------------------------------------------
// Problem shapes
//   x:      [32, 128, 56, 56]  fp32  (NCHW)
//   weight: [256, 128, 3, 3]   fp32  (OIHW)
//   bias:   [256]              fp32
//   out:    [32, 256, 56, 56]  fp32
//
// Exact int4 conv via bf16 tensor cores:
//   q in [-8,7] exact in bf16; products <=64; sums <=73728 < 2^24 -> fp32 acc exact.
// Quantization division uses div.full.f32 to match XLA:GPU's nvptx-prec-divf32=1
// lowering bit-for-bit.
// ---------------------------------------------------------------------------

#define B_      32
#define CIN_    128
#define H_      56
#define W_      56
#define COUT_   256
#define HW_     (H_ * W_)          // 3136
#define KDIM_   (CIN_ * 9)         // 1152
#define NX_     (B_ * CIN_ * HW_)  // 12845056
#define NW_     (COUT_ * CIN_ * 9) // 294912

// -------------------------- device scratch ---------------------------------
__device__ unsigned g_amax_x_bits;
__device__ unsigned g_amax_w_bits;
__device__ __align__(16) __nv_bfloat16 g_qx[NX_];            // quantized x, NCHW
__device__ __align__(16) __nv_bfloat16 g_qw[COUT_ * KDIM_];  // [co][k], k = tap*128 + ci

// XLA:GPU-compatible fp32 division (div.full.f32, <=2ulp, deterministic expansion)
__device__ __forceinline__ float xla_div(float a, float b) {
    float r;
    asm("div.full.f32 %0, %1, %2;" : "=f"(r) : "f"(a), "f"(b));
    return r;
}

// -------------------------- reset ------------------------------------------
__global__ void k_reset() {
    g_amax_x_bits = 0u;
    g_amax_w_bits = 0u;
}

// -------------------------- absmax (grid-stride, float4) -------------------
__global__ void k_absmax(const float* __restrict__ p, int n4, int which) {
    int tid  = threadIdx.x;
    int lane = tid & 31, warp = tid >> 5;
    float m = 0.0f;
    const float4* p4 = reinterpret_cast<const float4*>(p);
    for (long long i = (long long)blockIdx.x * blockDim.x + tid; i < n4;
         i += (long long)gridDim.x * blockDim.x) {
        float4 v = p4[i];
        m = fmaxf(m, fmaxf(fmaxf(fabsf(v.x), fabsf(v.y)),
                           fmaxf(fabsf(v.z), fabsf(v.w))));
    }
    #pragma unroll
    for (int off = 16; off; off >>= 1)
        m = fmaxf(m, __shfl_xor_sync(0xFFFFFFFFu, m, off));
    __shared__ float sm[8];
    if (lane == 0) sm[warp] = m;
    __syncthreads();
    if (warp == 0) {
        m = (lane < 8) ? sm[lane] : 0.0f;
        #pragma unroll
        for (int off = 4; off; off >>= 1)
            m = fmaxf(m, __shfl_xor_sync(0xFFFFFFFFu, m, off));
        if (lane == 0) {
            unsigned* tgt = which ? &g_amax_w_bits : &g_amax_x_bits;
            atomicMax(tgt, __float_as_uint(m));
        }
    }
}

__device__ __forceinline__ float quant1(float v, float s) {
    // Match XLA:GPU: clip(round_nearest_even(div.full(v, s)), -8, 7)
    float r = rintf(xla_div(v, s));
    return fminf(fmaxf(r, -8.0f), 7.0f);
}

// -------------------------- quantize x -------------------------------------
__global__ void k_quant_x(const float* __restrict__ x) {
    int i = blockIdx.x * blockDim.x + threadIdx.x;   // one float4 per thread
    float s = xla_div(__uint_as_float(g_amax_x_bits), 7.5f);
    float4 v = reinterpret_cast<const float4*>(x)[i];
    __nv_bfloat16 q0 = __float2bfloat16_rn(quant1(v.x, s));
    __nv_bfloat16 q1 = __float2bfloat16_rn(quant1(v.y, s));
    __nv_bfloat16 q2 = __float2bfloat16_rn(quant1(v.z, s));
    __nv_bfloat16 q3 = __float2bfloat16_rn(quant1(v.w, s));
    ushort4 pk;
    pk.x = *reinterpret_cast<unsigned short*>(&q0);
    pk.y = *reinterpret_cast<unsigned short*>(&q1);
    pk.z = *reinterpret_cast<unsigned short*>(&q2);
    pk.w = *reinterpret_cast<unsigned short*>(&q3);
    reinterpret_cast<ushort4*>(g_qx)[i] = pk;
}

// -------------------------- quantize + repack w ----------------------------
// src OIHW [co][ci][kh][kw] -> dst [co][k] with k = (kh*3+kw)*128 + ci
__global__ void k_quant_w(const float* __restrict__ w) {
    int idx = blockIdx.x * blockDim.x + threadIdx.x;  // 0 .. NW_-1
    float s = xla_div(__uint_as_float(g_amax_w_bits), 7.5f);
    int co  = idx / KDIM_;
    int rem = idx - co * KDIM_;
    int ci  = rem / 9;
    int t   = rem - ci * 9;           // kh*3+kw
    int k   = t * CIN_ + ci;
    g_qw[co * KDIM_ + k] = __float2bfloat16_rn(quant1(w[idx], s));
}

// -------------------------- conv (implicit GEMM, mma.sync bf16) ------------
// Block tile: M=128 (Cout), N=64 (pixels of one image), K-steps of 16.
// 8 warps: warp = wn*4 + wm ; warp tile 32(M) x 32(N).
// Per warp-kstep: 2 m16 A-frag tiles x 4 n8 B-frag tiles = 8 mma.
#define AS_LD 18
#define BS_LD 18

__global__ void __launch_bounds__(256, 2)
k_conv(const float* __restrict__ bias, float* __restrict__ out) {
    __shared__ __nv_bfloat16 As[128 * AS_LD];
    __shared__ __nv_bfloat16 Bs[64 * BS_LD];

    const int tid  = threadIdx.x;
    const int warp = tid >> 5, lane = tid & 31;
    const int g    = lane >> 2, tg = lane & 3;
    const int wm   = warp & 3;      // 0..3  -> M sub-tile of 32
    const int wn   = warp >> 2;     // 0..1  -> N sub-tile of 32
    const int m0   = blockIdx.x * 128;
    const int pix0 = blockIdx.y * 64;
    const int b    = blockIdx.z;

    float acc[2][4][4];
    #pragma unroll
    for (int mt = 0; mt < 2; mt++)
        #pragma unroll
        for (int nt = 0; nt < 4; nt++)
            #pragma unroll
            for (int i = 0; i < 4; i++) acc[mt][nt][i] = 0.0f;

    for (int ks = 0; ks < KDIM_ / 16; ks++) {
        const int k0  = ks * 16;
        const int tap = k0 >> 7;          // all 16 k in chunk share one tap
        const int ci0 = k0 & 127;
        const int dy  = tap / 3 - 1;
        const int dx  = tap % 3 - 1;

        // ---- load A: 128 x 16 from g_qw[co][k] (8B per thread x2) ----
        #pragma unroll
        for (int i = 0; i < 2; i++) {
            int v   = tid + i * 256;          // 0..511
            int r   = v >> 2;
            int kc4 = (v & 3) * 4;
            uint2 val = *reinterpret_cast<const uint2*>(
                &g_qw[(m0 + r) * KDIM_ + k0 + kc4]);
            *reinterpret_cast<unsigned*>(&As[r * AS_LD + kc4])     = val.x;
            *reinterpret_cast<unsigned*>(&As[r * AS_LD + kc4 + 2]) = val.y;
        }

        // ---- load B: 16 x 64 gathered from qx (stored transposed [n][k]) --
        #pragma unroll
        for (int i = 0; i < 4; i++) {
            int e  = tid + i * 256;           // 0..1023
            int n  = e & 63;
            int kc = e >> 6;
            int pix = pix0 + n;
            int h  = pix / 56;
            int w  = pix - h * 56;
            int hh = h + dy, ww = w + dx;
            __nv_bfloat16 val = __float2bfloat16_rn(0.0f);
            if ((unsigned)hh < 56u && (unsigned)ww < 56u)
                val = g_qx[((b * CIN_ + ci0 + kc) * H_ + hh) * W_ + ww];
            Bs[n * BS_LD + kc] = val;
        }
        __syncthreads();

        // ---- fragments ----
        unsigned a[2][4], bf[4][2];
        #pragma unroll
        for (int mt = 0; mt < 2; mt++) {
            int rb = wm * 32 + mt * 16;
            a[mt][0] = *reinterpret_cast<const unsigned*>(&As[(rb + g)     * AS_LD + tg * 2]);
            a[mt][1] = *reinterpret_cast<const unsigned*>(&As[(rb + g + 8) * AS_LD + tg * 2]);
            a[mt][2] = *reinterpret_cast<const unsigned*>(&As[(rb + g)     * AS_LD + tg * 2 + 8]);
            a[mt][3] = *reinterpret_cast<const unsigned*>(&As[(rb + g + 8) * AS_LD + tg * 2 + 8]);
        }
        #pragma unroll
        for (int nt = 0; nt < 4; nt++) {
            int n = wn * 32 + nt * 8 + g;
            bf[nt][0] = *reinterpret_cast<const unsigned*>(&Bs[n * BS_LD + tg * 2]);
            bf[nt][1] = *reinterpret_cast<const unsigned*>(&Bs[n * BS_LD + tg * 2 + 8]);
        }

        #pragma unroll
        for (int mt = 0; mt < 2; mt++)
            #pragma unroll
            for (int nt = 0; nt < 4; nt++) {
                asm volatile(
                    "mma.sync.aligned.m16n8k16.row.col.f32.bf16.bf16.f32 "
                    "{%0,%1,%2,%3}, {%4,%5,%6,%7}, {%8,%9}, {%0,%1,%2,%3};\n"
                    : "+f"(acc[mt][nt][0]), "+f"(acc[mt][nt][1]),
                      "+f"(acc[mt][nt][2]), "+f"(acc[mt][nt][3])
                    : "r"(a[mt][0]), "r"(a[mt][1]), "r"(a[mt][2]), "r"(a[mt][3]),
                      "r"(bf[nt][0]), "r"(bf[nt][1]));
            }
        __syncthreads();
    }

    // ---- epilogue: dequant + bias ----
    const float sx = xla_div(__uint_as_float(g_amax_x_bits), 7.5f);
    const float sw = xla_div(__uint_as_float(g_amax_w_bits), 7.5f);
    const float scale = sx * sw;
    #pragma unroll
    for (int mt = 0; mt < 2; mt++) {
        int co0 = m0 + wm * 32 + mt * 16;
        int r0  = co0 + g;
        int r1  = co0 + g + 8;
        float bias0 = bias[r0];
        float bias1 = bias[r1];
        #pragma unroll
        for (int nt = 0; nt < 4; nt++) {
            int n = pix0 + wn * 32 + nt * 8 + tg * 2;
            float2 v0, v1;
            v0.x = fmaf(acc[mt][nt][0], scale, bias0);
            v0.y = fmaf(acc[mt][nt][1], scale, bias0);
            v1.x = fmaf(acc[mt][nt][2], scale, bias1);
            v1.y = fmaf(acc[mt][nt][3], scale, bias1);
            *reinterpret_cast<float2*>(&out[((long long)b * COUT_ + r0) * HW_ + n]) = v0;
            *reinterpret_cast<float2*>(&out[((long long)b * COUT_ + r1) * HW_ + n]) = v1;
        }
    }
}

// ---------------------------------------------------------------------------
extern "C" void kernel_launch(void* const* d_in, const int* in_sizes, int n_in,
                              void* d_out, int out_size) {
    const float* x    = (const float*)d_in[0];
    const float* w    = (const float*)d_in[1];
    const float* bias = (const float*)d_in[2];
    float* out        = (float*)d_out;

    k_reset<<<1, 32>>>();
    k_absmax<<<4096, 256>>>(x, NX_ / 4, 0);
    k_absmax<<<288, 256>>>(w, NW_ / 4, 1);
    k_quant_x<<<NX_ / 4 / 256, 256>>>(x);
    k_quant_w<<<NW_ / 256, 256>>>(w);
    dim3 grid(COUT_ / 128, HW_ / 64, B_);
    k_conv<<<grid, 256>>>(bias, out);
}

// round 3
// speedup vs baseline: 1.0030x; 1.0030x over previous
#include <cuda_runtime.h>
#include <cuda_bf16.h>
#include <cstdint>

// ---------------------------------------------------------------------------
// Problem shapes
//   x:      [32, 128, 56, 56]  fp32  (NCHW)
//   weight: [256, 128, 3, 3]   fp32  (OIHW)
//   bias:   [256]              fp32
//   out:    [32, 256, 56, 56]  fp32
//
// Exact int4 conv via bf16 tensor cores:
//   q in [-8,7] exact in bf16; products <=64; sums <=73728 < 2^24 -> fp32 acc exact.
// Quantization division uses div.full.f32 to match XLA:GPU's nvptx-prec-divf32=1
// lowering bit-for-bit.
// ---------------------------------------------------------------------------

#define B_      32
#define CIN_    128
#define H_      56
#define W_      56
#define COUT_   256
#define HW_     (H_ * W_)          // 3136
#define KDIM_   (CIN_ * 9)         // 1152
#define NX_     (B_ * CIN_ * HW_)  // 12845056
#define NW_     (COUT_ * CIN_ * 9) // 294912

// -------------------------- device scratch ---------------------------------
__device__ unsigned g_amax_x_bits;
__device__ unsigned g_amax_w_bits;
__device__ __align__(16) __nv_bfloat16 g_qx[NX_];            // quantized x, NCHW
__device__ __align__(16) __nv_bfloat16 g_qw[COUT_ * KDIM_];  // [co][k], k = tap*128 + ci

// XLA:GPU-compatible fp32 division (div.full.f32, <=2ulp, deterministic expansion)
__device__ __forceinline__ float xla_div(float a, float b) {
    float r;
    asm("div.full.f32 %0, %1, %2;" : "=f"(r) : "f"(a), "f"(b));
    return r;
}

// -------------------------- reset ------------------------------------------
__global__ void k_reset() {
    g_amax_x_bits = 0u;
    g_amax_w_bits = 0u;
}

// -------------------------- absmax (grid-stride, float4) -------------------
__global__ void k_absmax(const float* __restrict__ p, int n4, int which) {
    int tid  = threadIdx.x;
    int lane = tid & 31, warp = tid >> 5;
    float m = 0.0f;
    const float4* p4 = reinterpret_cast<const float4*>(p);
    for (long long i = (long long)blockIdx.x * blockDim.x + tid; i < n4;
         i += (long long)gridDim.x * blockDim.x) {
        float4 v = p4[i];
        m = fmaxf(m, fmaxf(fmaxf(fabsf(v.x), fabsf(v.y)),
                           fmaxf(fabsf(v.z), fabsf(v.w))));
    }
    #pragma unroll
    for (int off = 16; off; off >>= 1)
        m = fmaxf(m, __shfl_xor_sync(0xFFFFFFFFu, m, off));
    __shared__ float sm[8];
    if (lane == 0) sm[warp] = m;
    __syncthreads();
    if (warp == 0) {
        m = (lane < 8) ? sm[lane] : 0.0f;
        #pragma unroll
        for (int off = 4; off; off >>= 1)
            m = fmaxf(m, __shfl_xor_sync(0xFFFFFFFFu, m, off));
        if (lane == 0) {
            unsigned* tgt = which ? &g_amax_w_bits : &g_amax_x_bits;
            atomicMax(tgt, __float_as_uint(m));
        }
    }
}

__device__ __forceinline__ float quant1(float v, float s) {
    // Match XLA:GPU: clip(round_nearest_even(div.full(v, s)), -8, 7)
    float r = rintf(xla_div(v, s));
    return fminf(fmaxf(r, -8.0f), 7.0f);
}

// -------------------------- quantize x -------------------------------------
__global__ void k_quant_x(const float* __restrict__ x) {
    int i = blockIdx.x * blockDim.x + threadIdx.x;   // one float4 per thread
    float s = xla_div(__uint_as_float(g_amax_x_bits), 7.5f);
    float4 v = reinterpret_cast<const float4*>(x)[i];
    __nv_bfloat16 q0 = __float2bfloat16_rn(quant1(v.x, s));
    __nv_bfloat16 q1 = __float2bfloat16_rn(quant1(v.y, s));
    __nv_bfloat16 q2 = __float2bfloat16_rn(quant1(v.z, s));
    __nv_bfloat16 q3 = __float2bfloat16_rn(quant1(v.w, s));
    ushort4 pk;
    pk.x = *reinterpret_cast<unsigned short*>(&q0);
    pk.y = *reinterpret_cast<unsigned short*>(&q1);
    pk.z = *reinterpret_cast<unsigned short*>(&q2);
    pk.w = *reinterpret_cast<unsigned short*>(&q3);
    reinterpret_cast<ushort4*>(g_qx)[i] = pk;
}

// -------------------------- quantize + repack w ----------------------------
// src OIHW [co][ci][kh][kw] -> dst [co][k] with k = (kh*3+kw)*128 + ci
__global__ void k_quant_w(const float* __restrict__ w) {
    int idx = blockIdx.x * blockDim.x + threadIdx.x;  // 0 .. NW_-1
    float s = xla_div(__uint_as_float(g_amax_w_bits), 7.5f);
    int co  = idx / KDIM_;
    int rem = idx - co * KDIM_;
    int ci  = rem / 9;
    int t   = rem - ci * 9;           // kh*3+kw
    int k   = t * CIN_ + ci;
    g_qw[co * KDIM_ + k] = __float2bfloat16_rn(quant1(w[idx], s));
}

// -------------------------- conv (implicit GEMM, mma.sync bf16) ------------
// Block tile: M=128 (Cout), N=64 (pixels of one image), K-steps of 16.
// 8 warps: warp = wn*4 + wm ; warp tile 32(M) x 32(N).
// Per warp-kstep: 2 m16 A-frag tiles x 4 n8 B-frag tiles = 8 mma.
#define AS_LD 18
#define BS_LD 18

__global__ void __launch_bounds__(256, 2)
k_conv(const float* __restrict__ bias, float* __restrict__ out) {
    __shared__ __nv_bfloat16 As[128 * AS_LD];
    __shared__ __nv_bfloat16 Bs[64 * BS_LD];

    const int tid  = threadIdx.x;
    const int warp = tid >> 5, lane = tid & 31;
    const int g    = lane >> 2, tg = lane & 3;
    const int wm   = warp & 3;      // 0..3  -> M sub-tile of 32
    const int wn   = warp >> 2;     // 0..1  -> N sub-tile of 32
    const int m0   = blockIdx.x * 128;
    const int pix0 = blockIdx.y * 64;
    const int b    = blockIdx.z;

    float acc[2][4][4];
    #pragma unroll
    for (int mt = 0; mt < 2; mt++)
        #pragma unroll
        for (int nt = 0; nt < 4; nt++)
            #pragma unroll
            for (int i = 0; i < 4; i++) acc[mt][nt][i] = 0.0f;

    for (int ks = 0; ks < KDIM_ / 16; ks++) {
        const int k0  = ks * 16;
        const int tap = k0 >> 7;          // all 16 k in chunk share one tap
        const int ci0 = k0 & 127;
        const int dy  = tap / 3 - 1;
        const int dx  = tap % 3 - 1;

        // ---- load A: 128 x 16 from g_qw[co][k] (8B per thread x2) ----
        #pragma unroll
        for (int i = 0; i < 2; i++) {
            int v   = tid + i * 256;          // 0..511
            int r   = v >> 2;
            int kc4 = (v & 3) * 4;
            uint2 val = *reinterpret_cast<const uint2*>(
                &g_qw[(m0 + r) * KDIM_ + k0 + kc4]);
            *reinterpret_cast<unsigned*>(&As[r * AS_LD + kc4])     = val.x;
            *reinterpret_cast<unsigned*>(&As[r * AS_LD + kc4 + 2]) = val.y;
        }

        // ---- load B: 16 x 64 gathered from qx (stored transposed [n][k]) --
        #pragma unroll
        for (int i = 0; i < 4; i++) {
            int e  = tid + i * 256;           // 0..1023
            int n  = e & 63;
            int kc = e >> 6;
            int pix = pix0 + n;
            int h  = pix / 56;
            int w  = pix - h * 56;
            int hh = h + dy, ww = w + dx;
            __nv_bfloat16 val = __float2bfloat16_rn(0.0f);
            if ((unsigned)hh < 56u && (unsigned)ww < 56u)
                val = g_qx[((b * CIN_ + ci0 + kc) * H_ + hh) * W_ + ww];
            Bs[n * BS_LD + kc] = val;
        }
        __syncthreads();

        // ---- fragments ----
        unsigned a[2][4], bf[4][2];
        #pragma unroll
        for (int mt = 0; mt < 2; mt++) {
            int rb = wm * 32 + mt * 16;
            a[mt][0] = *reinterpret_cast<const unsigned*>(&As[(rb + g)     * AS_LD + tg * 2]);
            a[mt][1] = *reinterpret_cast<const unsigned*>(&As[(rb + g + 8) * AS_LD + tg * 2]);
            a[mt][2] = *reinterpret_cast<const unsigned*>(&As[(rb + g)     * AS_LD + tg * 2 + 8]);
            a[mt][3] = *reinterpret_cast<const unsigned*>(&As[(rb + g + 8) * AS_LD + tg * 2 + 8]);
        }
        #pragma unroll
        for (int nt = 0; nt < 4; nt++) {
            int n = wn * 32 + nt * 8 + g;
            bf[nt][0] = *reinterpret_cast<const unsigned*>(&Bs[n * BS_LD + tg * 2]);
            bf[nt][1] = *reinterpret_cast<const unsigned*>(&Bs[n * BS_LD + tg * 2 + 8]);
        }

        #pragma unroll
        for (int mt = 0; mt < 2; mt++)
            #pragma unroll
            for (int nt = 0; nt < 4; nt++) {
                asm volatile(
                    "mma.sync.aligned.m16n8k16.row.col.f32.bf16.bf16.f32 "
                    "{%0,%1,%2,%3}, {%4,%5,%6,%7}, {%8,%9}, {%0,%1,%2,%3};\n"
                    : "+f"(acc[mt][nt][0]), "+f"(acc[mt][nt][1]),
                      "+f"(acc[mt][nt][2]), "+f"(acc[mt][nt][3])
                    : "r"(a[mt][0]), "r"(a[mt][1]), "r"(a[mt][2]), "r"(a[mt][3]),
                      "r"(bf[nt][0]), "r"(bf[nt][1]));
            }
        __syncthreads();
    }

    // ---- epilogue: dequant + bias ----
    const float sx = xla_div(__uint_as_float(g_amax_x_bits), 7.5f);
    const float sw = xla_div(__uint_as_float(g_amax_w_bits), 7.5f);
    const float scale = sx * sw;
    #pragma unroll
    for (int mt = 0; mt < 2; mt++) {
        int co0 = m0 + wm * 32 + mt * 16;
        int r0  = co0 + g;
        int r1  = co0 + g + 8;
        float bias0 = bias[r0];
        float bias1 = bias[r1];
        #pragma unroll
        for (int nt = 0; nt < 4; nt++) {
            int n = pix0 + wn * 32 + nt * 8 + tg * 2;
            float2 v0, v1;
            v0.x = fmaf(acc[mt][nt][0], scale, bias0);
            v0.y = fmaf(acc[mt][nt][1], scale, bias0);
            v1.x = fmaf(acc[mt][nt][2], scale, bias1);
            v1.y = fmaf(acc[mt][nt][3], scale, bias1);
            *reinterpret_cast<float2*>(&out[((long long)b * COUT_ + r0) * HW_ + n]) = v0;
            *reinterpret_cast<float2*>(&out[((long long)b * COUT_ + r1) * HW_ + n]) = v1;
        }
    }
}

// ---------------------------------------------------------------------------
extern "C" void kernel_launch(void* const* d_in, const int* in_sizes, int n_in,
                              void* d_out, int out_size) {
    const float* x    = (const float*)d_in[0];
    const float* w    = (const float*)d_in[1];
    const float* bias = (const float*)d_in[2];
    float* out        = (float*)d_out;

    k_reset<<<1, 32>>>();
    k_absmax<<<4096, 256>>>(x, NX_ / 4, 0);
    k_absmax<<<288, 256>>>(w, NW_ / 4, 1);
    k_quant_x<<<NX_ / 4 / 256, 256>>>(x);
    k_quant_w<<<NW_ / 256, 256>>>(w);
    dim3 grid(COUT_ / 128, HW_ / 64, B_);
    k_conv<<<grid, 256>>>(bias, out);
}

// round 6
// speedup vs baseline: 1.3303x; 1.3263x over previous
#include <cuda_runtime.h>
#include <cuda_bf16.h>
#include <cstdint>

#define B_      32
#define CIN_    128
#define H_      56
#define W_      56
#define COUT_   256
#define HW_     (H_ * W_)
#define KDIM_   (CIN_ * 9)
#define NX_     (B_ * CIN_ * HW_)
#define NW_     (COUT_ * CIN_ * 9)
#define XP_ROWS 58
#define XP_W    64
#define NXP_    (B_ * CIN_ * XP_ROWS * XP_W)

__device__ unsigned g_amax_x_bits;
__device__ unsigned g_amax_w_bits;
__device__ __align__(16) __nv_bfloat16 g_qxp[NXP_];          // padded, zero borders
__device__ __align__(16) __nv_bfloat16 g_qw[COUT_ * KDIM_];  // [co][tap*128+ci]

__device__ __forceinline__ float xla_div(float a, float b) {
    float r;
    asm("div.full.f32 %0, %1, %2;" : "=f"(r) : "f"(a), "f"(b));
    return r;
}
__device__ __forceinline__ float quant1(float v, float s) {
    float r = rintf(xla_div(v, s));
    return fminf(fmaxf(r, -8.0f), 7.0f);
}

__global__ void k_reset() { g_amax_x_bits = 0u; g_amax_w_bits = 0u; }

__global__ void k_absmax(const float* __restrict__ p, int n4, int which) {
    int tid = threadIdx.x, lane = tid & 31, warp = tid >> 5;
    float m = 0.0f;
    const float4* p4 = reinterpret_cast<const float4*>(p);
    for (long long i = (long long)blockIdx.x * blockDim.x + tid; i < n4;
         i += (long long)gridDim.x * blockDim.x) {
        float4 v = p4[i];
        m = fmaxf(m, fmaxf(fmaxf(fabsf(v.x), fabsf(v.y)), fmaxf(fabsf(v.z), fabsf(v.w))));
    }
    #pragma unroll
    for (int off = 16; off; off >>= 1) m = fmaxf(m, __shfl_xor_sync(~0u, m, off));
    __shared__ float sm[8];
    if (lane == 0) sm[warp] = m;
    __syncthreads();
    if (warp == 0) {
        m = (lane < 8) ? sm[lane] : 0.0f;
        #pragma unroll
        for (int off = 4; off; off >>= 1) m = fmaxf(m, __shfl_xor_sync(~0u, m, off));
        if (lane == 0) atomicMax(which ? &g_amax_w_bits : &g_amax_x_bits, __float_as_uint(m));
    }
}

// quantize x into padded [bc][hp 0..57][wp 0..63]; borders zero
__global__ void k_quant_xp(const float* __restrict__ x) {
    int idx = blockIdx.x * 256 + threadIdx.x;     // one 8-elem group
    int g = idx & 7;
    int rowIdx = idx >> 3;                        // bc*58 + hp
    int hp = rowIdx % XP_ROWS;
    int bc = rowIdx / XP_ROWS;
    float s = xla_div(__uint_as_float(g_amax_x_bits), 7.5f);
    unsigned short q[8];
    #pragma unroll
    for (int e = 0; e < 8; e++) q[e] = 0;
    if (hp >= 1 && hp <= 56) {
        const float* src = x + (long long)bc * HW_ + (hp - 1) * 56;
        #pragma unroll
        for (int e = 0; e < 8; e++) {
            int wp = g * 8 + e;
            if (wp >= 1 && wp <= 56) {
                __nv_bfloat16 h = __float2bfloat16_rn(quant1(src[wp - 1], s));
                q[e] = *reinterpret_cast<unsigned short*>(&h);
            }
        }
    }
    uint4 pk;
    pk.x = q[0] | ((unsigned)q[1] << 16);
    pk.y = q[2] | ((unsigned)q[3] << 16);
    pk.z = q[4] | ((unsigned)q[5] << 16);
    pk.w = q[6] | ((unsigned)q[7] << 16);
    *reinterpret_cast<uint4*>(&g_qxp[(long long)rowIdx * XP_W + g * 8]) = pk;
}

__global__ void k_quant_w(const float* __restrict__ w) {
    int idx = blockIdx.x * blockDim.x + threadIdx.x;
    float s = xla_div(__uint_as_float(g_amax_w_bits), 7.5f);
    int co = idx / KDIM_;
    int rem = idx - co * KDIM_;
    int ci = rem / 9;
    int t  = rem - ci * 9;
    g_qw[co * KDIM_ + t * CIN_ + ci] = __float2bfloat16_rn(quant1(w[idx], s));
}

// ---------------- conv: M=128 co x N=64 (one out row), cp.async pipelined ----
#define TS_W 68                   // halfs per wp row (pad for banks)
#define TS_R (66 * TS_W)          // halfs per input row
#define AS_LD 24                  // halfs per A row (48B rows: 16B-aligned, conflict-free)
#define ABUF (128 * AS_LD)        // halfs per A stage
#define NSTAGE 3

__global__ void __launch_bounds__(256, 2)
k_conv(const float* __restrict__ bias, float* __restrict__ out) {
    __shared__ __align__(16) unsigned short T[3 * TS_R];       // [r][wp<66][ci<64]
    __shared__ __align__(16) unsigned short A[NSTAGE * ABUF];  // 3-stage [co 128][k 16]

    const int tid = threadIdx.x, warp = tid >> 5, lane = tid & 31;
    const int g = lane >> 2, tg = lane & 3;
    const int wm = warp & 3, wn = warp >> 2;
    const int co0 = blockIdx.x * 128;
    const int h0  = blockIdx.y;                // output row
    const int b   = blockIdx.z;

    float acc[2][4][4];
    #pragma unroll
    for (int mt = 0; mt < 2; mt++)
        #pragma unroll
        for (int nt = 0; nt < 4; nt++)
            #pragma unroll
            for (int i = 0; i < 4; i++) acc[mt][nt][i] = 0.0f;

    const int ar = tid >> 1, ahc = tid & 1;    // A copy: row, 16B-half
    uint32_t a_dst_base = (uint32_t)__cvta_generic_to_shared(A) + (ar * AS_LD + ahc * 8) * 2;

    for (int cih = 0; cih < 2; cih++) {
        __syncthreads();                        // prior T/A reads done
        // ---- fill T: transpose 3 input rows x 64 ci x 64 wp ----
        #pragma unroll
        for (int i = 0; i < 6; i++) {
            int v = tid + i * 256;              // 0..1535
            int ci = v & 63, wpg = (v >> 6) & 7, r = v >> 9;
            const uint4 d = *reinterpret_cast<const uint4*>(
                g_qxp + (((long long)(b * CIN_ + cih * 64 + ci) * XP_ROWS) + (h0 + r)) * XP_W + wpg * 8);
            unsigned wv[4] = {d.x, d.y, d.z, d.w};
            #pragma unroll
            for (int e = 0; e < 8; e++)
                T[r * TS_R + (wpg * 8 + e) * TS_W + ci] =
                    (unsigned short)(wv[e >> 1] >> ((e & 1) * 16));
        }
        // ---- prefetch A stages 0..1 ----
        #pragma unroll
        for (int p = 0; p < 2; p++) {
            int k0 = (p >> 2) * CIN_ + cih * 64 + (p & 3) * 16;
            const void* src = &g_qw[(co0 + ar) * KDIM_ + k0 + ahc * 8];
            uint32_t dst = a_dst_base + p * ABUF * 2;
            asm volatile("cp.async.cg.shared.global [%0], [%1], 16;" :: "r"(dst), "l"(src));
            asm volatile("cp.async.commit_group;");
        }

        for (int s = 0; s < 36; s++) {
            const int buf = s % NSTAGE;
            if (s < 35) asm volatile("cp.async.wait_group 1;");
            else        asm volatile("cp.async.wait_group 0;");
            __syncthreads();

            const int tap = s >> 2, c16 = s & 3;
            const int rrow = tap / 3, dxp = tap % 3;

            // fragments
            unsigned af[2][4], bf[4][2];
            const unsigned short* Ab = A + buf * ABUF;
            #pragma unroll
            for (int mt = 0; mt < 2; mt++) {
                int rb = wm * 32 + mt * 16;
                af[mt][0] = *reinterpret_cast<const unsigned*>(&Ab[(rb + g)     * AS_LD + tg * 2]);
                af[mt][1] = *reinterpret_cast<const unsigned*>(&Ab[(rb + g + 8) * AS_LD + tg * 2]);
                af[mt][2] = *reinterpret_cast<const unsigned*>(&Ab[(rb + g)     * AS_LD + tg * 2 + 8]);
                af[mt][3] = *reinterpret_cast<const unsigned*>(&Ab[(rb + g + 8) * AS_LD + tg * 2 + 8]);
            }
            #pragma unroll
            for (int nt = 0; nt < 4; nt++) {
                int base = rrow * TS_R + (wn * 32 + nt * 8 + g + dxp) * TS_W + c16 * 16 + tg * 2;
                bf[nt][0] = *reinterpret_cast<const unsigned*>(&T[base]);
                bf[nt][1] = *reinterpret_cast<const unsigned*>(&T[base + 8]);
            }

            if (s + 2 < 36) {                  // prefetch stage s+2
                int p = s + 2;
                int k0 = (p >> 2) * CIN_ + cih * 64 + (p & 3) * 16;
                const void* src = &g_qw[(co0 + ar) * KDIM_ + k0 + ahc * 8];
                uint32_t dst = a_dst_base + (p % NSTAGE) * ABUF * 2;
                asm volatile("cp.async.cg.shared.global [%0], [%1], 16;" :: "r"(dst), "l"(src));
                asm volatile("cp.async.commit_group;");
            }

            #pragma unroll
            for (int mt = 0; mt < 2; mt++)
                #pragma unroll
                for (int nt = 0; nt < 4; nt++)
                    asm volatile(
                        "mma.sync.aligned.m16n8k16.row.col.f32.bf16.bf16.f32 "
                        "{%0,%1,%2,%3}, {%4,%5,%6,%7}, {%8,%9}, {%0,%1,%2,%3};\n"
                        : "+f"(acc[mt][nt][0]), "+f"(acc[mt][nt][1]),
                          "+f"(acc[mt][nt][2]), "+f"(acc[mt][nt][3])
                        : "r"(af[mt][0]), "r"(af[mt][1]), "r"(af[mt][2]), "r"(af[mt][3]),
                          "r"(bf[nt][0]), "r"(bf[nt][1]));
        }
        asm volatile("cp.async.wait_group 0;");
    }

    // ---- epilogue ----
    const float sx = xla_div(__uint_as_float(g_amax_x_bits), 7.5f);
    const float sw = xla_div(__uint_as_float(g_amax_w_bits), 7.5f);
    const float scale = sx * sw;
    #pragma unroll
    for (int mt = 0; mt < 2; mt++) {
        int r0 = co0 + wm * 32 + mt * 16 + g;
        int r1 = r0 + 8;
        float bias0 = bias[r0];
        float bias1 = bias[r1];
        #pragma unroll
        for (int nt = 0; nt < 4; nt++) {
            int n = wn * 32 + nt * 8 + tg * 2;
            if (n < 56) {
                float2 v0, v1;
                v0.x = fmaf(acc[mt][nt][0], scale, bias0);
                v0.y = fmaf(acc[mt][nt][1], scale, bias0);
                v1.x = fmaf(acc[mt][nt][2], scale, bias1);
                v1.y = fmaf(acc[mt][nt][3], scale, bias1);
                long long o0 = ((long long)b * COUT_ + r0) * HW_ + h0 * 56 + n;
                long long o1 = ((long long)b * COUT_ + r1) * HW_ + h0 * 56 + n;
                *reinterpret_cast<float2*>(&out[o0]) = v0;
                *reinterpret_cast<float2*>(&out[o1]) = v1;
            }
        }
    }
}

extern "C" void kernel_launch(void* const* d_in, const int* in_sizes, int n_in,
                              void* d_out, int out_size) {
    const float* x    = (const float*)d_in[0];
    const float* w    = (const float*)d_in[1];
    const float* bias = (const float*)d_in[2];
    float* out        = (float*)d_out;

    k_reset<<<1, 32>>>();
    k_absmax<<<4096, 256>>>(x, NX_ / 4, 0);
    k_absmax<<<288, 256>>>(w, NW_ / 4, 1);
    k_quant_xp<<<NXP_ / 8 / 256, 256>>>(x);
    k_quant_w<<<NW_ / 256, 256>>>(w);
    dim3 grid(COUT_ / 128, H_, B_);
    k_conv<<<grid, 256>>>(bias, out);
}

// round 8
// speedup vs baseline: 1.5376x; 1.1558x over previous
#include <cuda_runtime.h>
#include <cuda_bf16.h>
#include <cstdint>

#define B_      32
#define CIN_    128
#define H_      56
#define W_      56
#define COUT_   256
#define HW_     (H_ * W_)
#define KDIM_   (CIN_ * 9)
#define NX_     (B_ * CIN_ * HW_)
#define NW_     (COUT_ * CIN_ * 9)
#define XP_ROWS 58
#define XP_W    64
#define NXP_    (B_ * CIN_ * XP_ROWS * XP_W)

__device__ unsigned g_amax_x_bits;
__device__ unsigned g_amax_w_bits;
__device__ __align__(16) __nv_bfloat16 g_qxp[NXP_];          // padded, zero borders
__device__ __align__(16) __nv_bfloat16 g_qw[COUT_ * KDIM_];  // [co][tap*128+ci]

__device__ __forceinline__ float xla_div(float a, float b) {
    float r;
    asm("div.full.f32 %0, %1, %2;" : "=f"(r) : "f"(a), "f"(b));
    return r;
}
__device__ __forceinline__ float quant1(float v, float s) {
    float r = rintf(xla_div(v, s));
    return fminf(fmaxf(r, -8.0f), 7.0f);
}

__global__ void k_reset() { g_amax_x_bits = 0u; g_amax_w_bits = 0u; }

__global__ void k_absmax(const float* __restrict__ p, int n4, int which) {
    int tid = threadIdx.x, lane = tid & 31, warp = tid >> 5;
    float m = 0.0f;
    const float4* p4 = reinterpret_cast<const float4*>(p);
    for (long long i = (long long)blockIdx.x * blockDim.x + tid; i < n4;
         i += (long long)gridDim.x * blockDim.x) {
        float4 v = p4[i];
        m = fmaxf(m, fmaxf(fmaxf(fabsf(v.x), fabsf(v.y)), fmaxf(fabsf(v.z), fabsf(v.w))));
    }
    #pragma unroll
    for (int off = 16; off; off >>= 1) m = fmaxf(m, __shfl_xor_sync(~0u, m, off));
    __shared__ float sm[8];
    if (lane == 0) sm[warp] = m;
    __syncthreads();
    if (warp == 0) {
        m = (lane < 8) ? sm[lane] : 0.0f;
        #pragma unroll
        for (int off = 4; off; off >>= 1) m = fmaxf(m, __shfl_xor_sync(~0u, m, off));
        if (lane == 0) atomicMax(which ? &g_amax_w_bits : &g_amax_x_bits, __float_as_uint(m));
    }
}

// quantize x into padded [bc][hp 0..57][wp 0..63]; borders zero
__global__ void k_quant_xp(const float* __restrict__ x) {
    int idx = blockIdx.x * 256 + threadIdx.x;     // one 8-elem group
    int g = idx & 7;
    int rowIdx = idx >> 3;                        // bc*58 + hp
    int hp = rowIdx % XP_ROWS;
    int bc = rowIdx / XP_ROWS;
    float s = xla_div(__uint_as_float(g_amax_x_bits), 7.5f);
    unsigned short q[8];
    #pragma unroll
    for (int e = 0; e < 8; e++) q[e] = 0;
    if (hp >= 1 && hp <= 56) {
        const float* src = x + (long long)bc * HW_ + (hp - 1) * 56;
        #pragma unroll
        for (int e = 0; e < 8; e++) {
            int wp = g * 8 + e;
            if (wp >= 1 && wp <= 56) {
                __nv_bfloat16 h = __float2bfloat16_rn(quant1(src[wp - 1], s));
                q[e] = *reinterpret_cast<unsigned short*>(&h);
            }
        }
    }
    uint4 pk;
    pk.x = q[0] | ((unsigned)q[1] << 16);
    pk.y = q[2] | ((unsigned)q[3] << 16);
    pk.z = q[4] | ((unsigned)q[5] << 16);
    pk.w = q[6] | ((unsigned)q[7] << 16);
    *reinterpret_cast<uint4*>(&g_qxp[(long long)rowIdx * XP_W + g * 8]) = pk;
}

__global__ void k_quant_w(const float* __restrict__ w) {
    int idx = blockIdx.x * blockDim.x + threadIdx.x;
    float s = xla_div(__uint_as_float(g_amax_w_bits), 7.5f);
    int co = idx / KDIM_;
    int rem = idx - co * KDIM_;
    int ci = rem / 9;
    int t  = rem - ci * 9;
    g_qw[co * KDIM_ + t * CIN_ + ci] = __float2bfloat16_rn(quant1(w[idx], s));
}

// ---------------- conv: M=128 co x N=64 (one out row), ldmatrix + cp.async ----
#define TS_W 72                   // halfs per wp row (144B: conflict-free ldmatrix)
#define TS_R (66 * TS_W)          // halfs per input row
#define AS_LD 24                  // halfs per A row (48B rows)
#define ABUF (128 * AS_LD)        // halfs per A stage
#define NSTAGE 3

__global__ void __launch_bounds__(256, 2)
k_conv(const float* __restrict__ bias, float* __restrict__ out) {
    __shared__ __align__(16) unsigned short T[3 * TS_R];       // [r][wp<66][ci<64]
    __shared__ __align__(16) unsigned short A[NSTAGE * ABUF];  // 3-stage [co 128][k 16]

    const int tid = threadIdx.x, warp = tid >> 5, lane = tid & 31;
    const int wm = warp & 3, wn = warp >> 2;
    const int co0 = blockIdx.x * 128;
    const int h0  = blockIdx.y;                // output row
    const int b   = blockIdx.z;

    float acc[2][4][4];
    #pragma unroll
    for (int mt = 0; mt < 2; mt++)
        #pragma unroll
        for (int nt = 0; nt < 4; nt++)
            #pragma unroll
            for (int i = 0; i < 4; i++) acc[mt][nt][i] = 0.0f;

    const int ar = tid >> 1, ahc = tid & 1;    // A copy: row, 16B-half
    const uint32_t Abase = (uint32_t)__cvta_generic_to_shared(A);
    const uint32_t Tbase = (uint32_t)__cvta_generic_to_shared(T);
    const uint32_t a_dst_base = Abase + (ar * AS_LD + ahc * 8) * 2;

    // ldmatrix lane offsets (bytes), constant across iterations
    const int quad = lane >> 3, lr = lane & 7;
    uint32_t aoff[2], boff[2];
    #pragma unroll
    for (int mt = 0; mt < 2; mt++)
        aoff[mt] = ((wm * 32 + mt * 16 + (quad & 1) * 8 + lr) * AS_LD + (quad >> 1) * 8) * 2;
    #pragma unroll
    for (int pr = 0; pr < 2; pr++)
        boff[pr] = ((wn * 32 + (pr * 2 + (quad >> 1)) * 8 + lr) * TS_W + (quad & 1) * 8) * 2;

    for (int cih = 0; cih < 2; cih++) {
        __syncthreads();                        // prior T/A reads done
        // ---- fill T: transpose 3 input rows x 64 ci x 64 wp ----
        #pragma unroll
        for (int i = 0; i < 6; i++) {
            int v = tid + i * 256;              // 0..1535
            int ci = v & 63, wpg = (v >> 6) & 7, r = v >> 9;
            const uint4 d = *reinterpret_cast<const uint4*>(
                g_qxp + (((long long)(b * CIN_ + cih * 64 + ci) * XP_ROWS) + (h0 + r)) * XP_W + wpg * 8);
            unsigned wv[4] = {d.x, d.y, d.z, d.w};
            #pragma unroll
            for (int e = 0; e < 8; e++)
                T[r * TS_R + (wpg * 8 + e) * TS_W + ci] =
                    (unsigned short)(wv[e >> 1] >> ((e & 1) * 16));
        }
        // ---- prefetch A stages 0..1 ----
        #pragma unroll
        for (int p = 0; p < 2; p++) {
            int k0 = cih * 64 + (p & 3) * 16;
            const void* src = &g_qw[(co0 + ar) * KDIM_ + k0 + ahc * 8];
            uint32_t dst = a_dst_base + p * ABUF * 2;
            asm volatile("cp.async.cg.shared.global [%0], [%1], 16;" :: "r"(dst), "l"(src));
            asm volatile("cp.async.commit_group;");
        }

        for (int s = 0; s < 36; s++) {
            const int buf = s % NSTAGE;
            if (s < 35) asm volatile("cp.async.wait_group 1;");
            else        asm volatile("cp.async.wait_group 0;");
            __syncthreads();

            const int tap = s >> 2, c16 = s & 3;
            const int rrow = tap / 3, dxp = tap % 3;

            // ---- fragments via ldmatrix ----
            unsigned af[2][4], bf[4][2];
            const uint32_t abufb = Abase + buf * ABUF * 2;
            #pragma unroll
            for (int mt = 0; mt < 2; mt++)
                asm volatile("ldmatrix.sync.aligned.m8n8.x4.shared.b16 {%0,%1,%2,%3}, [%4];"
                    : "=r"(af[mt][0]), "=r"(af[mt][1]), "=r"(af[mt][2]), "=r"(af[mt][3])
                    : "r"(abufb + aoff[mt]));
            const uint32_t bcom = Tbase + (rrow * TS_R + dxp * TS_W + c16 * 16) * 2;
            #pragma unroll
            for (int pr = 0; pr < 2; pr++)
                asm volatile("ldmatrix.sync.aligned.m8n8.x4.shared.b16 {%0,%1,%2,%3}, [%4];"
                    : "=r"(bf[pr * 2][0]), "=r"(bf[pr * 2][1]),
                      "=r"(bf[pr * 2 + 1][0]), "=r"(bf[pr * 2 + 1][1])
                    : "r"(bcom + boff[pr]));

            if (s + 2 < 36) {                  // prefetch stage s+2
                int p = s + 2;
                int k0 = (p >> 2) * CIN_ + cih * 64 + (p & 3) * 16;
                const void* src = &g_qw[(co0 + ar) * KDIM_ + k0 + ahc * 8];
                uint32_t dst = a_dst_base + (p % NSTAGE) * ABUF * 2;
                asm volatile("cp.async.cg.shared.global [%0], [%1], 16;" :: "r"(dst), "l"(src));
                asm volatile("cp.async.commit_group;");
            }

            #pragma unroll
            for (int mt = 0; mt < 2; mt++)
                #pragma unroll
                for (int nt = 0; nt < 4; nt++)
                    asm volatile(
                        "mma.sync.aligned.m16n8k16.row.col.f32.bf16.bf16.f32 "
                        "{%0,%1,%2,%3}, {%4,%5,%6,%7}, {%8,%9}, {%0,%1,%2,%3};\n"
                        : "+f"(acc[mt][nt][0]), "+f"(acc[mt][nt][1]),
                          "+f"(acc[mt][nt][2]), "+f"(acc[mt][nt][3])
                        : "r"(af[mt][0]), "r"(af[mt][1]), "r"(af[mt][2]), "r"(af[mt][3]),
                          "r"(bf[nt][0]), "r"(bf[nt][1]));
        }
        asm volatile("cp.async.wait_group 0;");
    }

    // ---- epilogue ----
    const int g = lane >> 2, tg = lane & 3;
    const float sx = xla_div(__uint_as_float(g_amax_x_bits), 7.5f);
    const float sw = xla_div(__uint_as_float(g_amax_w_bits), 7.5f);
    const float scale = sx * sw;
    #pragma unroll
    for (int mt = 0; mt < 2; mt++) {
        int r0 = co0 + wm * 32 + mt * 16 + g;
        int r1 = r0 + 8;
        float bias0 = bias[r0];
        float bias1 = bias[r1];
        #pragma unroll
        for (int nt = 0; nt < 4; nt++) {
            int n = wn * 32 + nt * 8 + tg * 2;
            if (n < 56) {
                float2 v0, v1;
                v0.x = fmaf(acc[mt][nt][0], scale, bias0);
                v0.y = fmaf(acc[mt][nt][1], scale, bias0);
                v1.x = fmaf(acc[mt][nt][2], scale, bias1);
                v1.y = fmaf(acc[mt][nt][3], scale, bias1);
                long long o0 = ((long long)b * COUT_ + r0) * HW_ + h0 * 56 + n;
                long long o1 = ((long long)b * COUT_ + r1) * HW_ + h0 * 56 + n;
                *reinterpret_cast<float2*>(&out[o0]) = v0;
                *reinterpret_cast<float2*>(&out[o1]) = v1;
            }
        }
    }
}

extern "C" void kernel_launch(void* const* d_in, const int* in_sizes, int n_in,
                              void* d_out, int out_size) {
    const float* x    = (const float*)d_in[0];
    const float* w    = (const float*)d_in[1];
    const float* bias = (const float*)d_in[2];
    float* out        = (float*)d_out;

    k_reset<<<1, 32>>>();
    k_absmax<<<4096, 256>>>(x, NX_ / 4, 0);
    k_absmax<<<288, 256>>>(w, NW_ / 4, 1);
    k_quant_xp<<<NXP_ / 8 / 256, 256>>>(x);
    k_quant_w<<<NW_ / 256, 256>>>(w);
    dim3 grid(COUT_ / 128, H_, B_);
    k_conv<<<grid, 256>>>(bias, out);
}

// round 9
// speedup vs baseline: 3.0105x; 1.9579x over previous
#include <cuda_runtime.h>
#include <cuda_bf16.h>
#include <cstdint>

#define B_      32
#define CIN_    128
#define H_      56
#define W_      56
#define COUT_   256
#define HW_     (H_ * W_)
#define KDIM_   (CIN_ * 9)
#define NX_     (B_ * CIN_ * HW_)
#define NW_     (COUT_ * CIN_ * 9)
#define XP_ROWS 58

__device__ unsigned g_amax_x_bits;
__device__ unsigned g_amax_w_bits;
// activations, quantized s8, pre-transposed: [b][hp 0..57][wp 0..63][ci 0..127]
__device__ __align__(16) char g_qxp[B_ * XP_ROWS * 64 * 128];
// weights, quantized s8: [co][tap*128 + ci]
__device__ __align__(16) char g_qw[COUT_ * KDIM_];

__device__ __forceinline__ float xla_div(float a, float b) {
    float r;
    asm("div.full.f32 %0, %1, %2;" : "=f"(r) : "f"(a), "f"(b));
    return r;
}
__device__ __forceinline__ float quant1(float v, float s) {
    float r = rintf(xla_div(v, s));
    return fminf(fmaxf(r, -8.0f), 7.0f);
}

__global__ void k_reset() { g_amax_x_bits = 0u; g_amax_w_bits = 0u; }

__global__ void k_absmax(const float* __restrict__ p, int n4, int which) {
    int tid = threadIdx.x, lane = tid & 31, warp = tid >> 5;
    float m = 0.0f;
    const float4* p4 = reinterpret_cast<const float4*>(p);
    for (long long i = (long long)blockIdx.x * blockDim.x + tid; i < n4;
         i += (long long)gridDim.x * blockDim.x) {
        float4 v = p4[i];
        m = fmaxf(m, fmaxf(fmaxf(fabsf(v.x), fabsf(v.y)), fmaxf(fabsf(v.z), fabsf(v.w))));
    }
    #pragma unroll
    for (int off = 16; off; off >>= 1) m = fmaxf(m, __shfl_xor_sync(~0u, m, off));
    __shared__ float sm[8];
    if (lane == 0) sm[warp] = m;
    __syncthreads();
    if (warp == 0) {
        m = (lane < 8) ? sm[lane] : 0.0f;
        #pragma unroll
        for (int off = 4; off; off >>= 1) m = fmaxf(m, __shfl_xor_sync(~0u, m, off));
        if (lane == 0) atomicMax(which ? &g_amax_w_bits : &g_amax_x_bits, __float_as_uint(m));
    }
}

// quantize + transpose x: one block per (hp, b). Output row (b,hp): [wp][ci] s8.
__global__ void k_quant_xt(const float* __restrict__ x) {
    __shared__ char sq[64 * 132];         // [wp][ci], rows padded to 132B
    const int tid = threadIdx.x;
    const int hp = blockIdx.x, b = blockIdx.y;
    char* dst = g_qxp + ((long long)(b * XP_ROWS + hp) * 64) * 128;

    if (hp == 0 || hp == 57) {            // border: zeros
        #pragma unroll
        for (int j = 0; j < 8; j++)
            *reinterpret_cast<unsigned*>(dst + tid * 32 + j * 4) = 0u;
        return;
    }
    // zero staging (covers wp=0, wp>=57, and ci-gaps none)
    for (int i = tid * 4; i < 64 * 132; i += 256 * 4)
        *reinterpret_cast<unsigned*>(sq + i) = 0u;
    __syncthreads();

    const float s = xla_div(__uint_as_float(g_amax_x_bits), 7.5f);
    // 128 ci x 14 float4 groups = 1792 loads
    #pragma unroll
    for (int i = 0; i < 7; i++) {
        int v = i * 256 + tid;            // 0..1791
        int ci = v / 14, wg = v - ci * 14;
        const float4 d = *reinterpret_cast<const float4*>(
            x + ((long long)(b * CIN_ + ci) * H_ + (hp - 1)) * W_ + wg * 4);
        float q0 = quant1(d.x, s), q1 = quant1(d.y, s);
        float q2 = quant1(d.z, s), q3 = quant1(d.w, s);
        int wp = wg * 4 + 1;              // w = wg*4 -> wp = w+1
        sq[(wp + 0) * 132 + ci] = (char)(int)q0;
        sq[(wp + 1) * 132 + ci] = (char)(int)q1;
        sq[(wp + 2) * 132 + ci] = (char)(int)q2;
        sq[(wp + 3) * 132 + ci] = (char)(int)q3;
    }
    __syncthreads();
    // write out coalesced: thread t -> wp = t/4, ci chunk = (t%4)*32
    {
        int wp = tid >> 2, ci0 = (tid & 3) * 32;
        #pragma unroll
        for (int j = 0; j < 8; j++)
            *reinterpret_cast<unsigned*>(dst + wp * 128 + ci0 + j * 4) =
                *reinterpret_cast<const unsigned*>(sq + wp * 132 + ci0 + j * 4);
    }
}

__global__ void k_quant_w(const float* __restrict__ w) {
    int idx = blockIdx.x * blockDim.x + threadIdx.x;
    float s = xla_div(__uint_as_float(g_amax_w_bits), 7.5f);
    int co = idx / KDIM_;
    int rem = idx - co * KDIM_;
    int ci = rem / 9;
    int t  = rem - ci * 9;
    g_qw[co * KDIM_ + t * CIN_ + ci] = (char)(int)quant1(w[idx], s);
}

// ---------------- conv: s8 IMMA, M=128 co x N=64 (one out row) ----------------
#define TS_W  80                    // bytes per wp row (conflict-free, 16B-aligned)
#define TS_R  (66 * TS_W)           // bytes per input row (5280)
#define AS_LD 48                    // bytes per A row (32 data + pad)
#define ABUF  (128 * AS_LD)         // bytes per A stage (6144)

__global__ void __launch_bounds__(256, 2)
k_conv(const float* __restrict__ bias, float* __restrict__ out) {
    __shared__ __align__(16) char T[3 * TS_R];     // [r][wp<66][ci 64 of cih]
    __shared__ __align__(16) char A[3 * ABUF];     // 3-stage [co 128][k 32]

    const int tid = threadIdx.x, warp = tid >> 5, lane = tid & 31;
    const int wm = warp & 3, wn = warp >> 2;
    const int co0 = blockIdx.x * 128;
    const int h0  = blockIdx.y;                    // output row
    const int b   = blockIdx.z;

    int acc[2][4][4];
    #pragma unroll
    for (int mt = 0; mt < 2; mt++)
        #pragma unroll
        for (int nt = 0; nt < 4; nt++)
            #pragma unroll
            for (int i = 0; i < 4; i++) acc[mt][nt][i] = 0;

    const int arow = tid >> 1, ahalf = tid & 1;    // A copy: row, 16B-half
    const uint32_t Abase = (uint32_t)__cvta_generic_to_shared(A);
    const uint32_t Tbase = (uint32_t)__cvta_generic_to_shared(T);
    const uint32_t a_dst = Abase + arow * AS_LD + ahalf * 16;

    // ldmatrix lane offsets (bytes)
    const int quad = lane >> 3, lr = lane & 7;
    uint32_t aoff[2], boff[2];
    #pragma unroll
    for (int mt = 0; mt < 2; mt++)
        aoff[mt] = (wm * 32 + mt * 16 + (quad & 1) * 8 + lr) * AS_LD + (quad >> 1) * 16;
    #pragma unroll
    for (int pr = 0; pr < 2; pr++)
        boff[pr] = (wn * 32 + (pr * 2 + (quad >> 1)) * 8 + lr) * TS_W + (quad & 1) * 16;

    for (int cih = 0; cih < 2; cih++) {
        __syncthreads();                           // prior T/A reads done
        // ---- fill T: 3 rows x 64 wp x 64 ci bytes, plain 16B copies ----
        #pragma unroll
        for (int i = 0; i < 3; i++) {
            int v = i * 256 + tid;                 // 0..767
            int ch = v & 3, wp = (v >> 2) & 63, r = v >> 8;
            const uint4 d = *reinterpret_cast<const uint4*>(
                g_qxp + ((long long)((b * XP_ROWS + h0 + r) * 64 + wp)) * 128 + cih * 64 + ch * 16);
            *reinterpret_cast<uint4*>(T + r * TS_R + wp * TS_W + ch * 16) = d;
        }
        // ---- prefetch A stages 0..1 ----
        #pragma unroll
        for (int p = 0; p < 2; p++) {
            const void* src = g_qw + (co0 + arow) * KDIM_ + (p >> 1) * 128 + cih * 64 + (p & 1) * 32 + ahalf * 16;
            uint32_t dst = a_dst + p * ABUF;
            asm volatile("cp.async.cg.shared.global [%0], [%1], 16;" :: "r"(dst), "l"(src));
            asm volatile("cp.async.commit_group;");
        }

        for (int s = 0; s < 18; s++) {
            const int buf = s % 3;
            if (s < 17) asm volatile("cp.async.wait_group 1;");
            else        asm volatile("cp.async.wait_group 0;");
            __syncthreads();

            const int tap = s >> 1, c = s & 1;
            const int rrow = tap / 3, dxp = tap % 3;

            unsigned af[2][4], bf[4][2];
            const uint32_t abufb = Abase + buf * ABUF;
            #pragma unroll
            for (int mt = 0; mt < 2; mt++)
                asm volatile("ldmatrix.sync.aligned.m8n8.x4.shared.b16 {%0,%1,%2,%3}, [%4];"
                    : "=r"(af[mt][0]), "=r"(af[mt][1]), "=r"(af[mt][2]), "=r"(af[mt][3])
                    : "r"(abufb + aoff[mt]));
            const uint32_t bcom = Tbase + rrow * TS_R + dxp * TS_W + c * 32;
            #pragma unroll
            for (int pr = 0; pr < 2; pr++)
                asm volatile("ldmatrix.sync.aligned.m8n8.x4.shared.b16 {%0,%1,%2,%3}, [%4];"
                    : "=r"(bf[pr * 2][0]), "=r"(bf[pr * 2][1]),
                      "=r"(bf[pr * 2 + 1][0]), "=r"(bf[pr * 2 + 1][1])
                    : "r"(bcom + boff[pr]));

            if (s + 2 < 18) {                      // prefetch stage s+2
                int p = s + 2;
                const void* src = g_qw + (co0 + arow) * KDIM_ + (p >> 1) * 128 + cih * 64 + (p & 1) * 32 + ahalf * 16;
                uint32_t dst = a_dst + (p % 3) * ABUF;
                asm volatile("cp.async.cg.shared.global [%0], [%1], 16;" :: "r"(dst), "l"(src));
                asm volatile("cp.async.commit_group;");
            }

            #pragma unroll
            for (int mt = 0; mt < 2; mt++)
                #pragma unroll
                for (int nt = 0; nt < 4; nt++)
                    asm volatile(
                        "mma.sync.aligned.m16n8k32.row.col.s32.s8.s8.s32 "
                        "{%0,%1,%2,%3}, {%4,%5,%6,%7}, {%8,%9}, {%0,%1,%2,%3};\n"
                        : "+r"(acc[mt][nt][0]), "+r"(acc[mt][nt][1]),
                          "+r"(acc[mt][nt][2]), "+r"(acc[mt][nt][3])
                        : "r"(af[mt][0]), "r"(af[mt][1]), "r"(af[mt][2]), "r"(af[mt][3]),
                          "r"(bf[nt][0]), "r"(bf[nt][1]));
        }
        asm volatile("cp.async.wait_group 0;");
    }

    // ---- epilogue ----
    const int g = lane >> 2, tg = lane & 3;
    const float sx = xla_div(__uint_as_float(g_amax_x_bits), 7.5f);
    const float sw = xla_div(__uint_as_float(g_amax_w_bits), 7.5f);
    const float scale = sx * sw;
    #pragma unroll
    for (int mt = 0; mt < 2; mt++) {
        int r0 = co0 + wm * 32 + mt * 16 + g;
        int r1 = r0 + 8;
        float bias0 = bias[r0];
        float bias1 = bias[r1];
        #pragma unroll
        for (int nt = 0; nt < 4; nt++) {
            int n = wn * 32 + nt * 8 + tg * 2;
            if (n < 56) {
                float2 v0, v1;
                v0.x = fmaf((float)acc[mt][nt][0], scale, bias0);
                v0.y = fmaf((float)acc[mt][nt][1], scale, bias0);
                v1.x = fmaf((float)acc[mt][nt][2], scale, bias1);
                v1.y = fmaf((float)acc[mt][nt][3], scale, bias1);
                long long o0 = ((long long)b * COUT_ + r0) * HW_ + h0 * 56 + n;
                long long o1 = ((long long)b * COUT_ + r1) * HW_ + h0 * 56 + n;
                *reinterpret_cast<float2*>(&out[o0]) = v0;
                *reinterpret_cast<float2*>(&out[o1]) = v1;
            }
        }
    }
}

extern "C" void kernel_launch(void* const* d_in, const int* in_sizes, int n_in,
                              void* d_out, int out_size) {
    const float* x    = (const float*)d_in[0];
    const float* w    = (const float*)d_in[1];
    const float* bias = (const float*)d_in[2];
    float* out        = (float*)d_out;

    k_reset<<<1, 32>>>();
    k_absmax<<<4096, 256>>>(x, NX_ / 4, 0);
    k_absmax<<<288, 256>>>(w, NW_ / 4, 1);
    {
        dim3 gq(XP_ROWS, B_);
        k_quant_xt<<<gq, 256>>>(x);
    }
    k_quant_w<<<NW_ / 256, 256>>>(w);
    dim3 grid(COUT_ / 128, H_, B_);
    k_conv<<<grid, 256>>>(bias, out);
}

// round 10
// speedup vs baseline: 4.0282x; 1.3380x over previous
#include <cuda_runtime.h>
#include <cuda_bf16.h>
#include <cstdint>

#define B_      32
#define CIN_    128
#define H_      56
#define W_      56
#define COUT_   256
#define HW_     (H_ * W_)
#define KDIM_   (CIN_ * 9)
#define NX_     (B_ * CIN_ * HW_)
#define NW_     (COUT_ * CIN_ * 9)
#define XP_ROWS 58

__device__ unsigned g_amax_x_bits;
__device__ unsigned g_amax_w_bits;
// activations, quantized s8, pre-transposed: [b][hp 0..57][wp 0..63][ci 0..127]
__device__ __align__(16) char g_qxp[B_ * XP_ROWS * 64 * 128];
// weights, quantized s8: [co][tap*128 + ci]
__device__ __align__(16) char g_qw[COUT_ * KDIM_];

__device__ __forceinline__ float xla_div(float a, float b) {
    float r;
    asm("div.full.f32 %0, %1, %2;" : "=f"(r) : "f"(a), "f"(b));
    return r;
}
__device__ __forceinline__ float quant1(float v, float s) {
    float r = rintf(xla_div(v, s));
    return fminf(fmaxf(r, -8.0f), 7.0f);
}

__global__ void k_reset() { g_amax_x_bits = 0u; g_amax_w_bits = 0u; }

__global__ void k_absmax(const float* __restrict__ p, int n4, int which) {
    int tid = threadIdx.x, lane = tid & 31, warp = tid >> 5;
    float m = 0.0f;
    const float4* p4 = reinterpret_cast<const float4*>(p);
    for (long long i = (long long)blockIdx.x * blockDim.x + tid; i < n4;
         i += (long long)gridDim.x * blockDim.x) {
        float4 v = p4[i];
        m = fmaxf(m, fmaxf(fmaxf(fabsf(v.x), fabsf(v.y)), fmaxf(fabsf(v.z), fabsf(v.w))));
    }
    #pragma unroll
    for (int off = 16; off; off >>= 1) m = fmaxf(m, __shfl_xor_sync(~0u, m, off));
    __shared__ float sm[8];
    if (lane == 0) sm[warp] = m;
    __syncthreads();
    if (warp == 0) {
        m = (lane < 8) ? sm[lane] : 0.0f;
        #pragma unroll
        for (int off = 4; off; off >>= 1) m = fmaxf(m, __shfl_xor_sync(~0u, m, off));
        if (lane == 0) atomicMax(which ? &g_amax_w_bits : &g_amax_x_bits, __float_as_uint(m));
    }
}

// quantize + transpose x: one block per (hp, b). Output row (b,hp): [wp][ci] s8.
__global__ void k_quant_xt(const float* __restrict__ x) {
    __shared__ char sq[64 * 132];         // [wp][ci], rows padded to 132B
    const int tid = threadIdx.x;
    const int hp = blockIdx.x, b = blockIdx.y;
    char* dst = g_qxp + ((long long)(b * XP_ROWS + hp) * 64) * 128;

    if (hp == 0 || hp == 57) {            // border: zeros
        #pragma unroll
        for (int j = 0; j < 8; j++)
            *reinterpret_cast<unsigned*>(dst + tid * 32 + j * 4) = 0u;
        return;
    }
    for (int i = tid * 4; i < 64 * 132; i += 256 * 4)
        *reinterpret_cast<unsigned*>(sq + i) = 0u;
    __syncthreads();

    const float s = xla_div(__uint_as_float(g_amax_x_bits), 7.5f);
    #pragma unroll
    for (int i = 0; i < 7; i++) {
        int v = i * 256 + tid;            // 0..1791
        int ci = v / 14, wg = v - ci * 14;
        const float4 d = *reinterpret_cast<const float4*>(
            x + ((long long)(b * CIN_ + ci) * H_ + (hp - 1)) * W_ + wg * 4);
        float q0 = quant1(d.x, s), q1 = quant1(d.y, s);
        float q2 = quant1(d.z, s), q3 = quant1(d.w, s);
        int wp = wg * 4 + 1;
        sq[(wp + 0) * 132 + ci] = (char)(int)q0;
        sq[(wp + 1) * 132 + ci] = (char)(int)q1;
        sq[(wp + 2) * 132 + ci] = (char)(int)q2;
        sq[(wp + 3) * 132 + ci] = (char)(int)q3;
    }
    __syncthreads();
    {
        int wp = tid >> 2, ci0 = (tid & 3) * 32;
        #pragma unroll
        for (int j = 0; j < 8; j++)
            *reinterpret_cast<unsigned*>(dst + wp * 128 + ci0 + j * 4) =
                *reinterpret_cast<const unsigned*>(sq + wp * 132 + ci0 + j * 4);
    }
}

__global__ void k_quant_w(const float* __restrict__ w) {
    int idx = blockIdx.x * blockDim.x + threadIdx.x;
    float s = xla_div(__uint_as_float(g_amax_w_bits), 7.5f);
    int co = idx / KDIM_;
    int rem = idx - co * KDIM_;
    int ci = rem / 9;
    int t  = rem - ci * 9;
    g_qw[co * KDIM_ + t * CIN_ + ci] = (char)(int)quant1(w[idx], s);
}

// ---- conv: s8 IMMA, M=128 co x N=128 (two out rows), K=64/iter, 3-stage ----
#define AS_LD 80                    // bytes per A row (64 data + 16 pad)
#define ABUF  (128 * AS_LD)         // 10240 per stage
#define TS_W  80                    // bytes per wp row
#define TS_R  (66 * TS_W)           // 5280 per input row
#define OFF_T (3 * ABUF)            // 30720
#define SMEM_CONV (OFF_T + 4 * TS_R)  // 51840

__global__ void __launch_bounds__(256, 2)
k_conv(const float* __restrict__ bias, float* __restrict__ out) {
    extern __shared__ __align__(16) char smem[];
    char* A = smem;
    char* T = smem + OFF_T;

    const int tid = threadIdx.x, warp = tid >> 5, lane = tid & 31;
    const int wm = warp & 3, wn = warp >> 2;      // wn = output row select
    const int co0 = blockIdx.x * 128;
    const int h0  = blockIdx.y * 2;               // output rows h0, h0+1
    const int b   = blockIdx.z;

    int acc[2][8][4];
    #pragma unroll
    for (int mt = 0; mt < 2; mt++)
        #pragma unroll
        for (int nt = 0; nt < 8; nt++)
            #pragma unroll
            for (int i = 0; i < 4; i++) acc[mt][nt][i] = 0;

    const uint32_t Abase = (uint32_t)__cvta_generic_to_shared(A);
    const uint32_t Tbase = (uint32_t)__cvta_generic_to_shared(T);

    const int quad = lane >> 3, lr = lane & 7;
    uint32_t aoff[2], boff[4];
    #pragma unroll
    for (int mt = 0; mt < 2; mt++)
        aoff[mt] = (wm * 32 + mt * 16 + (quad & 1) * 8 + lr) * AS_LD + (quad >> 1) * 16;
    #pragma unroll
    for (int pr = 0; pr < 4; pr++)
        boff[pr] = ((pr * 2 + (quad >> 1)) * 8 + lr) * TS_W + (quad & 1) * 16;

    for (int cih = 0; cih < 2; cih++) {
        __syncthreads();                           // prior T/A reads done
        // ---- fill T: 4 rows x 64 wp x 64 ci bytes ----
        #pragma unroll
        for (int i = 0; i < 4; i++) {
            int v = i * 256 + tid;                 // 0..1023
            int ch = v & 3, wp = (v >> 2) & 63, r = v >> 8;
            const uint4 d = *reinterpret_cast<const uint4*>(
                g_qxp + ((long long)((b * XP_ROWS + h0 + r) * 64 + wp)) * 128 + cih * 64 + ch * 16);
            *reinterpret_cast<uint4*>(T + r * TS_R + wp * TS_W + ch * 16) = d;
        }
        // ---- prefetch A taps 0,1 ----
        #pragma unroll
        for (int p = 0; p < 2; p++) {
            #pragma unroll
            for (int i = 0; i < 2; i++) {
                int v = tid + i * 256;             // 0..511
                int row = v >> 2, ch = v & 3;
                const void* src = g_qw + (co0 + row) * KDIM_ + p * CIN_ + cih * 64 + ch * 16;
                uint32_t dst = Abase + p * ABUF + row * AS_LD + ch * 16;
                asm volatile("cp.async.cg.shared.global [%0], [%1], 16;" :: "r"(dst), "l"(src));
            }
            asm volatile("cp.async.commit_group;");
        }

        for (int s = 0; s < 9; s++) {
            if (s < 8) asm volatile("cp.async.wait_group 1;");
            else       asm volatile("cp.async.wait_group 0;");
            __syncthreads();

            const int rrow = s / 3, dxp = s % 3;
            const uint32_t abufb = Abase + (s % 3) * ABUF;
            const uint32_t bbase = Tbase + (rrow + wn) * TS_R + dxp * TS_W;

            if (s + 2 < 9) {                       // prefetch tap s+2
                int p = s + 2;
                #pragma unroll
                for (int i = 0; i < 2; i++) {
                    int v = tid + i * 256;
                    int row = v >> 2, ch = v & 3;
                    const void* src = g_qw + (co0 + row) * KDIM_ + p * CIN_ + cih * 64 + ch * 16;
                    uint32_t dst = Abase + (p % 3) * ABUF + row * AS_LD + ch * 16;
                    asm volatile("cp.async.cg.shared.global [%0], [%1], 16;" :: "r"(dst), "l"(src));
                }
                asm volatile("cp.async.commit_group;");
            }

            #pragma unroll
            for (int c = 0; c < 2; c++) {          // K32 chunks of the tap
                unsigned af[2][4], bf[8][2];
                #pragma unroll
                for (int mt = 0; mt < 2; mt++)
                    asm volatile("ldmatrix.sync.aligned.m8n8.x4.shared.b16 {%0,%1,%2,%3}, [%4];"
                        : "=r"(af[mt][0]), "=r"(af[mt][1]), "=r"(af[mt][2]), "=r"(af[mt][3])
                        : "r"(abufb + aoff[mt] + c * 32));
                #pragma unroll
                for (int pr = 0; pr < 4; pr++)
                    asm volatile("ldmatrix.sync.aligned.m8n8.x4.shared.b16 {%0,%1,%2,%3}, [%4];"
                        : "=r"(bf[pr * 2][0]), "=r"(bf[pr * 2][1]),
                          "=r"(bf[pr * 2 + 1][0]), "=r"(bf[pr * 2 + 1][1])
                        : "r"(bbase + boff[pr] + c * 32));
                #pragma unroll
                for (int mt = 0; mt < 2; mt++)
                    #pragma unroll
                    for (int nt = 0; nt < 8; nt++)
                        asm volatile(
                            "mma.sync.aligned.m16n8k32.row.col.s32.s8.s8.s32 "
                            "{%0,%1,%2,%3}, {%4,%5,%6,%7}, {%8,%9}, {%0,%1,%2,%3};\n"
                            : "+r"(acc[mt][nt][0]), "+r"(acc[mt][nt][1]),
                              "+r"(acc[mt][nt][2]), "+r"(acc[mt][nt][3])
                            : "r"(af[mt][0]), "r"(af[mt][1]), "r"(af[mt][2]), "r"(af[mt][3]),
                              "r"(bf[nt][0]), "r"(bf[nt][1]));
            }
        }
        asm volatile("cp.async.wait_group 0;");
    }

    // ---- epilogue ----
    const int g = lane >> 2, tg = lane & 3;
    const float sx = xla_div(__uint_as_float(g_amax_x_bits), 7.5f);
    const float sw = xla_div(__uint_as_float(g_amax_w_bits), 7.5f);
    const float scale = sx * sw;
    const int h = h0 + wn;
    #pragma unroll
    for (int mt = 0; mt < 2; mt++) {
        int r0 = co0 + wm * 32 + mt * 16 + g;
        int r1 = r0 + 8;
        float bias0 = bias[r0];
        float bias1 = bias[r1];
        #pragma unroll
        for (int nt = 0; nt < 8; nt++) {
            int n = nt * 8 + tg * 2;
            if (n < 56) {
                float2 v0, v1;
                v0.x = fmaf((float)acc[mt][nt][0], scale, bias0);
                v0.y = fmaf((float)acc[mt][nt][1], scale, bias0);
                v1.x = fmaf((float)acc[mt][nt][2], scale, bias1);
                v1.y = fmaf((float)acc[mt][nt][3], scale, bias1);
                long long o0 = ((long long)b * COUT_ + r0) * HW_ + h * 56 + n;
                long long o1 = ((long long)b * COUT_ + r1) * HW_ + h * 56 + n;
                *reinterpret_cast<float2*>(&out[o0]) = v0;
                *reinterpret_cast<float2*>(&out[o1]) = v1;
            }
        }
    }
}

extern "C" void kernel_launch(void* const* d_in, const int* in_sizes, int n_in,
                              void* d_out, int out_size) {
    const float* x    = (const float*)d_in[0];
    const float* w    = (const float*)d_in[1];
    const float* bias = (const float*)d_in[2];
    float* out        = (float*)d_out;

    cudaFuncSetAttribute(k_conv, cudaFuncAttributeMaxDynamicSharedMemorySize, SMEM_CONV);
    k_reset<<<1, 32>>>();
    k_absmax<<<4096, 256>>>(x, NX_ / 4, 0);
    k_absmax<<<288, 256>>>(w, NW_ / 4, 1);
    {
        dim3 gq(XP_ROWS, B_);
        k_quant_xt<<<gq, 256>>>(x);
    }
    k_quant_w<<<NW_ / 256, 256>>>(w);
    dim3 grid(COUT_ / 128, H_ / 2, B_);
    k_conv<<<grid, 256, SMEM_CONV>>>(bias, out);
}